// round 5
// baseline (speedup 1.0000x reference)
#include <cuda_runtime.h>

#define DIM 64
#define MAX_NODES 100000
#define MAX_EDGES 1600000
#define SCAN_BS 1024

typedef unsigned long long ull;

// ---- device scratch (no allocs allowed) ----
__device__ __align__(16) float g_h[MAX_NODES * DIM];     // h = x + aggr
__device__ int  g_cnt[MAX_NODES];                        // degree histogram
__device__ int  g_offpart[MAX_NODES];                    // per-block exclusive scan
__device__ int  g_bsum[128];                             // block sums for scan
__device__ int  g_off[MAX_NODES + 1];                    // final offsets
__device__ int  g_cur[MAX_NODES];                        // scatter cursors
__device__ __align__(8) int2 g_edges[MAX_EDGES];         // (src, edge_id) sorted by dst

__device__ __forceinline__ ull pk2(float lo, float hi) {
    ull r; asm("mov.b64 %0, {%1, %2};" : "=l"(r) : "f"(lo), "f"(hi)); return r;
}
__device__ __forceinline__ void upk2(float& lo, float& hi, ull v) {
    asm("mov.b64 {%0, %1}, %2;" : "=f"(lo), "=f"(hi) : "l"(v));
}
__device__ __forceinline__ void ffma2(ull& d, ull a, ull b) {
    asm("fma.rn.f32x2 %0, %1, %2, %0;" : "+l"(d) : "l"(a), "l"(b));
}

// ---------------------------------------------------------------------------
// Phase A: dst-bucket construction (counting sort, int atomics only)
// ---------------------------------------------------------------------------
__global__ void zero_cnt_kernel(int N) {
    int i = blockIdx.x * blockDim.x + threadIdx.x;
    if (i < N) g_cnt[i] = 0;
}

__global__ void hist_kernel(const int* __restrict__ ei, int E) {
    int e = blockIdx.x * blockDim.x + threadIdx.x;
    if (e < E) atomicAdd(&g_cnt[ei[E + e]], 1);
}

__global__ void __launch_bounds__(SCAN_BS) scan1_kernel(int N) {
    const int tid = threadIdx.x;
    const int lane = tid & 31, wid = tid >> 5;
    const int i = blockIdx.x * SCAN_BS + tid;
    int c = (i < N) ? g_cnt[i] : 0;

    int v = c;
#pragma unroll
    for (int d = 1; d < 32; d <<= 1) {
        int t = __shfl_up_sync(0xFFFFFFFFu, v, d);
        if (lane >= d) v += t;
    }
    __shared__ int ws[32];
    if (lane == 31) ws[wid] = v;
    __syncthreads();
    if (wid == 0) {
        int s = ws[lane];
#pragma unroll
        for (int d = 1; d < 32; d <<= 1) {
            int t = __shfl_up_sync(0xFFFFFFFFu, s, d);
            if (lane >= d) s += t;
        }
        ws[lane] = s;
    }
    __syncthreads();
    const int base = (wid > 0) ? ws[wid - 1] : 0;
    const int incl = v + base;
    if (i < N) g_offpart[i] = incl - c;
    if (tid == SCAN_BS - 1) g_bsum[blockIdx.x] = incl;
}

__global__ void __launch_bounds__(128) scan2_kernel(int nb) {
    const int tid = threadIdx.x;
    const int lane = tid & 31, wid = tid >> 5;
    int c = (tid < nb) ? g_bsum[tid] : 0;
    int v = c;
#pragma unroll
    for (int d = 1; d < 32; d <<= 1) {
        int t = __shfl_up_sync(0xFFFFFFFFu, v, d);
        if (lane >= d) v += t;
    }
    __shared__ int ws[4];
    if (lane == 31) ws[wid] = v;
    __syncthreads();
    int base = 0;
#pragma unroll
    for (int w = 0; w < 4; w++) if (w < wid) base += ws[w];
    if (tid < nb) g_bsum[tid] = (v + base) - c;   // exclusive
}

__global__ void __launch_bounds__(SCAN_BS) scan3_kernel(int N, int E) {
    const int i = blockIdx.x * SCAN_BS + threadIdx.x;
    if (i < N) {
        const int o = g_offpart[i] + g_bsum[blockIdx.x];
        g_off[i] = o;
        g_cur[i] = o;
    }
    if (blockIdx.x == 0 && threadIdx.x == 0) g_off[N] = E;
}

__global__ void scatter_kernel(const int* __restrict__ ei, int E) {
    int e = blockIdx.x * blockDim.x + threadIdx.x;
    if (e < E) {
        const int dst = ei[E + e];
        const int p = atomicAdd(&g_cur[dst], 1);
        g_edges[p] = make_int2(ei[e], e);
    }
}

// ---------------------------------------------------------------------------
// Phase B: per-node aggregation. One warp per node, lane owns cols (2l, 2l+1).
// h[n] = x[n] + sum_{e: dst=n} relu(x[src_e] + ea_e @ We + be)
// - 32-edge chunk records loaded coalesced (lane l -> edge beg+l), shuffled out
// - 4 edges per group: 16 ea ulonglong2 loads + 4 x loads before any FMA
// - invalid tail lanes alias edge 0, masked by a 0/1 multiplier
// ---------------------------------------------------------------------------
__global__ void __launch_bounds__(256) aggregate_kernel(
    const float* __restrict__ x,
    const float* __restrict__ ea,       // [E, 16]
    const float* __restrict__ We,       // [16, 64]
    const float* __restrict__ be,       // [64]
    int N)
{
    __shared__ ull Wp[8 * DIM];         // packed K-pairs of We: Wp[k2*64+j]
    const int tid = threadIdx.x;
    for (int f = tid; f < 8 * DIM; f += 256) {
        const int k2 = f >> 6, j = f & 63;
        Wp[f] = pk2(We[(2 * k2) * DIM + j], We[(2 * k2 + 1) * DIM + j]);
    }
    __syncthreads();

    const int lane = tid & 31;
    const int c0 = lane * 2;
    const int n = (blockIdx.x * blockDim.x + tid) >> 5;
    if (n >= N) return;

    ull wA[8], wB[8];
#pragma unroll
    for (int k2 = 0; k2 < 8; k2++) {
        wA[k2] = Wp[k2 * 64 + c0];
        wB[k2] = Wp[k2 * 64 + c0 + 1];
    }
    const float2 bev = *reinterpret_cast<const float2*>(be + c0);
    const ulonglong2* __restrict__ eau = reinterpret_cast<const ulonglong2*>(ea);

    const int beg = g_off[n];
    const int end = g_off[n + 1];

    // issue the x[n] base load early
    const float2 xn = *reinterpret_cast<const float2*>(x + (size_t)n * DIM + c0);

    float acc0 = 0.f, acc1 = 0.f;

    for (int base = beg; base < end; base += 32) {
        const int m = min(32, end - base);
        int2 er = make_int2(0, 0);
        if (base + lane < end) er = g_edges[base + lane];

        for (int j = 0; j < m; j += 4) {
            int   s[4], id[4];
            float vf[4];
#pragma unroll
            for (int k = 0; k < 4; k++) {
                s[k]  = __shfl_sync(0xFFFFFFFFu, er.x, j + k);
                id[k] = __shfl_sync(0xFFFFFFFFu, er.y, j + k);
                vf[k] = (j + k < m) ? 1.f : 0.f;   // invalid lanes held (0,0): valid addrs
            }

            // issue ALL loads for the 4 edges before any FMA
            ull a[4][8];
            float2 xv[4];
#pragma unroll
            for (int k = 0; k < 4; k++) {
                const ulonglong2* ep = eau + (size_t)id[k] * 4;
                const ulonglong2 u0 = ep[0];
                const ulonglong2 u1 = ep[1];
                const ulonglong2 u2 = ep[2];
                const ulonglong2 u3 = ep[3];
                a[k][0] = u0.x; a[k][1] = u0.y;
                a[k][2] = u1.x; a[k][3] = u1.y;
                a[k][4] = u2.x; a[k][5] = u2.y;
                a[k][6] = u3.x; a[k][7] = u3.y;
                xv[k] = *reinterpret_cast<const float2*>(x + (size_t)s[k] * DIM + c0);
            }

            ull A[4], B[4];
#pragma unroll
            for (int k = 0; k < 4; k++) { A[k] = 0ull; B[k] = 0ull; }
#pragma unroll
            for (int k2 = 0; k2 < 8; k2++) {
#pragma unroll
                for (int k = 0; k < 4; k++) {
                    ffma2(A[k], a[k][k2], wA[k2]);
                    ffma2(B[k], a[k][k2], wB[k2]);
                }
            }
#pragma unroll
            for (int k = 0; k < 4; k++) {
                float lo0, hi0, lo1, hi1;
                upk2(lo0, hi0, A[k]);
                upk2(lo1, hi1, B[k]);
                acc0 += vf[k] * fmaxf(xv[k].x + (lo0 + hi0 + bev.x), 0.f);
                acc1 += vf[k] * fmaxf(xv[k].y + (lo1 + hi1 + bev.y), 0.f);
            }
        }
    }

    *reinterpret_cast<float2*>(g_h + (size_t)n * DIM + c0) =
        make_float2(xn.x + acc0, xn.y + acc1);
}

// ---------------------------------------------------------------------------
// Phase C: out = relu(h@W1 + b1) @ W2 + b2
// ---------------------------------------------------------------------------
#define HS_LD 68
#define MLP_SMEM (128 * HS_LD * 4 + 32 * 64 * 8)

__global__ void __launch_bounds__(256) mlp_kernel(
    const float* __restrict__ W1, const float* __restrict__ b1,
    const float* __restrict__ W2, const float* __restrict__ b2,
    float* __restrict__ out, int N)
{
    extern __shared__ float smem[];
    float* hs = smem;
    ull*   Wp = reinterpret_cast<ull*>(smem + 128 * HS_LD);

    const int tid = threadIdx.x;
    const int nb = blockIdx.x * 128;

#pragma unroll
    for (int f = tid; f < 128 * 16; f += 256) {
        const int i = f >> 4, c4 = f & 15;
        float4 v = make_float4(0.f, 0.f, 0.f, 0.f);
        if (nb + i < N) v = reinterpret_cast<const float4*>(g_h)[(size_t)(nb + i) * 16 + c4];
        *reinterpret_cast<float4*>(hs + i * HS_LD + c4 * 4) = v;
    }
    for (int f = tid; f < 2048; f += 256) {
        const int k2 = f >> 6, j = f & 63;
        Wp[f] = pk2(W1[(2 * k2) * DIM + j], W1[(2 * k2 + 1) * DIM + j]);
    }
    __syncthreads();

    const int rg = tid >> 4, jg = tid & 15;
    const int i0 = rg * 8, j0 = jg * 4;
    float t[8][4];

    {
        ull acc[8][4];
#pragma unroll
        for (int ii = 0; ii < 8; ii++)
#pragma unroll
            for (int jj = 0; jj < 4; jj++) acc[ii][jj] = 0ull;
#pragma unroll 8
        for (int k2 = 0; k2 < 32; k2++) {
            ull hv[8];
#pragma unroll
            for (int ii = 0; ii < 8; ii++)
                hv[ii] = *reinterpret_cast<const ull*>(hs + (i0 + ii) * HS_LD + 2 * k2);
            const ulonglong2 w01 = *reinterpret_cast<const ulonglong2*>(Wp + k2 * 64 + j0);
            const ulonglong2 w23 = *reinterpret_cast<const ulonglong2*>(Wp + k2 * 64 + j0 + 2);
            ull wv[4] = { w01.x, w01.y, w23.x, w23.y };
#pragma unroll
            for (int ii = 0; ii < 8; ii++)
#pragma unroll
                for (int jj = 0; jj < 4; jj++) ffma2(acc[ii][jj], hv[ii], wv[jj]);
        }
        const float4 bb = *reinterpret_cast<const float4*>(b1 + j0);
        const float bbv[4] = { bb.x, bb.y, bb.z, bb.w };
#pragma unroll
        for (int ii = 0; ii < 8; ii++)
#pragma unroll
            for (int jj = 0; jj < 4; jj++) {
                float lo, hi;
                upk2(lo, hi, acc[ii][jj]);
                t[ii][jj] = fmaxf(lo + hi + bbv[jj], 0.f);
            }
    }
    __syncthreads();

#pragma unroll
    for (int ii = 0; ii < 8; ii++)
        *reinterpret_cast<float4*>(hs + (i0 + ii) * HS_LD + j0) =
            make_float4(t[ii][0], t[ii][1], t[ii][2], t[ii][3]);
    for (int f = tid; f < 2048; f += 256) {
        const int k2 = f >> 6, j = f & 63;
        Wp[f] = pk2(W2[(2 * k2) * DIM + j], W2[(2 * k2 + 1) * DIM + j]);
    }
    __syncthreads();

    {
        ull acc[8][4];
#pragma unroll
        for (int ii = 0; ii < 8; ii++)
#pragma unroll
            for (int jj = 0; jj < 4; jj++) acc[ii][jj] = 0ull;
#pragma unroll 8
        for (int k2 = 0; k2 < 32; k2++) {
            ull hv[8];
#pragma unroll
            for (int ii = 0; ii < 8; ii++)
                hv[ii] = *reinterpret_cast<const ull*>(hs + (i0 + ii) * HS_LD + 2 * k2);
            const ulonglong2 w01 = *reinterpret_cast<const ulonglong2*>(Wp + k2 * 64 + j0);
            const ulonglong2 w23 = *reinterpret_cast<const ulonglong2*>(Wp + k2 * 64 + j0 + 2);
            ull wv[4] = { w01.x, w01.y, w23.x, w23.y };
#pragma unroll
            for (int ii = 0; ii < 8; ii++)
#pragma unroll
                for (int jj = 0; jj < 4; jj++) ffma2(acc[ii][jj], hv[ii], wv[jj]);
        }
        const float4 bb = *reinterpret_cast<const float4*>(b2 + j0);
        const float bbv[4] = { bb.x, bb.y, bb.z, bb.w };
#pragma unroll
        for (int ii = 0; ii < 8; ii++) {
            const int n = nb + i0 + ii;
            if (n < N) {
                float r[4];
#pragma unroll
                for (int jj = 0; jj < 4; jj++) {
                    float lo, hi;
                    upk2(lo, hi, acc[ii][jj]);
                    r[jj] = lo + hi + bbv[jj];
                }
                *reinterpret_cast<float4*>(out + (size_t)n * DIM + j0) =
                    make_float4(r[0], r[1], r[2], r[3]);
            }
        }
    }
}

// ---------------------------------------------------------------------------
extern "C" void kernel_launch(void* const* d_in, const int* in_sizes, int n_in,
                              void* d_out, int out_size)
{
    const float* x  = (const float*)d_in[0];
    const int*   ei = (const int*)d_in[1];        // int32 (JAX x64 disabled)
    const float* ea = (const float*)d_in[2];
    const float* We = (const float*)d_in[3];
    const float* be = (const float*)d_in[4];
    const float* W1 = (const float*)d_in[5];
    const float* b1 = (const float*)d_in[6];
    const float* W2 = (const float*)d_in[7];
    const float* b2 = (const float*)d_in[8];
    float* out = (float*)d_out;

    const int N = in_sizes[0] / DIM;       // 100000
    const int E = in_sizes[1] / 2;         // 1600000

    const int nbN   = (N + 255) / 256;
    const int nbE   = (E + 255) / 256;
    const int nbScn = (N + SCAN_BS - 1) / SCAN_BS;   // 98 (<=128)

    // A) dst-bucket counting sort
    zero_cnt_kernel<<<nbN, 256>>>(N);
    hist_kernel<<<nbE, 256>>>(ei, E);
    scan1_kernel<<<nbScn, SCAN_BS>>>(N);
    scan2_kernel<<<1, 128>>>(nbScn);
    scan3_kernel<<<nbScn, SCAN_BS>>>(N, E);
    scatter_kernel<<<nbE, 256>>>(ei, E);

    // B) gather-side aggregation: one warp per node, chunked records + 4-edge ILP
    aggregate_kernel<<<(N * 32 + 255) / 256, 256>>>(x, ea, We, be, N);

    // C) node MLP
    cudaFuncSetAttribute(mlp_kernel, cudaFuncAttributeMaxDynamicSharedMemorySize, MLP_SMEM);
    mlp_kernel<<<(N + 127) / 128, 256, MLP_SMEM>>>(W1, b1, W2, b2, out, N);
}

// round 6
// speedup vs baseline: 1.6925x; 1.6925x over previous
#include <cuda_runtime.h>

#define DIM 64
#define MAX_NODES 100000
#define MAX_EDGES 1600000
#define SCAN_BS 1024

typedef unsigned long long ull;

// ---- device scratch (no allocs allowed) ----
__device__ __align__(16) float g_h[MAX_NODES * DIM];       // h = x + aggr
__device__ __align__(16) float4 g_easrt[MAX_EDGES * 4];    // dst-sorted edge_attr rows
__device__ int  g_src[MAX_EDGES];                          // dst-sorted src ids
__device__ int  g_cnt[MAX_NODES];
__device__ int  g_offpart[MAX_NODES];
__device__ int  g_bsum[128];
__device__ int  g_off[MAX_NODES + 1];
__device__ int  g_cur[MAX_NODES];

__device__ __forceinline__ ull pk2(float lo, float hi) {
    ull r; asm("mov.b64 %0, {%1, %2};" : "=l"(r) : "f"(lo), "f"(hi)); return r;
}
__device__ __forceinline__ void upk2(float& lo, float& hi, ull v) {
    asm("mov.b64 {%0, %1}, %2;" : "=f"(lo), "=f"(hi) : "l"(v));
}
__device__ __forceinline__ void ffma2(ull& d, ull a, ull b) {
    asm("fma.rn.f32x2 %0, %1, %2, %0;" : "+l"(d) : "l"(a), "l"(b));
}
__device__ __forceinline__ unsigned smem_u32(const void* p) {
    unsigned a;
    asm("{ .reg .u64 t; cvta.to.shared.u64 t, %1; cvt.u32.u64 %0, t; }"
        : "=r"(a) : "l"(p));
    return a;
}
__device__ __forceinline__ void cpa16(unsigned s, const void* g) {
    asm volatile("cp.async.ca.shared.global [%0], [%1], 16;" :: "r"(s), "l"(g));
}

// ---------------------------------------------------------------------------
// Phase A: dst-bucket counting sort (payload-carrying)
// ---------------------------------------------------------------------------
__global__ void zero_cnt_kernel(int N) {
    int i = blockIdx.x * blockDim.x + threadIdx.x;
    if (i < N) g_cnt[i] = 0;
}

__global__ void hist_kernel(const int* __restrict__ ei, int E) {
    int e = blockIdx.x * blockDim.x + threadIdx.x;
    if (e < E) atomicAdd(&g_cnt[ei[E + e]], 1);
}

__global__ void __launch_bounds__(SCAN_BS) scan1_kernel(int N) {
    const int tid = threadIdx.x;
    const int lane = tid & 31, wid = tid >> 5;
    const int i = blockIdx.x * SCAN_BS + tid;
    int c = (i < N) ? g_cnt[i] : 0;
    int v = c;
#pragma unroll
    for (int d = 1; d < 32; d <<= 1) {
        int t = __shfl_up_sync(0xFFFFFFFFu, v, d);
        if (lane >= d) v += t;
    }
    __shared__ int ws[32];
    if (lane == 31) ws[wid] = v;
    __syncthreads();
    if (wid == 0) {
        int s = ws[lane];
#pragma unroll
        for (int d = 1; d < 32; d <<= 1) {
            int t = __shfl_up_sync(0xFFFFFFFFu, s, d);
            if (lane >= d) s += t;
        }
        ws[lane] = s;
    }
    __syncthreads();
    const int base = (wid > 0) ? ws[wid - 1] : 0;
    const int incl = v + base;
    if (i < N) g_offpart[i] = incl - c;
    if (tid == SCAN_BS - 1) g_bsum[blockIdx.x] = incl;
}

__global__ void __launch_bounds__(128) scan2_kernel(int nb) {
    const int tid = threadIdx.x;
    const int lane = tid & 31, wid = tid >> 5;
    int c = (tid < nb) ? g_bsum[tid] : 0;
    int v = c;
#pragma unroll
    for (int d = 1; d < 32; d <<= 1) {
        int t = __shfl_up_sync(0xFFFFFFFFu, v, d);
        if (lane >= d) v += t;
    }
    __shared__ int ws[4];
    if (lane == 31) ws[wid] = v;
    __syncthreads();
    int base = 0;
#pragma unroll
    for (int w = 0; w < 4; w++) if (w < wid) base += ws[w];
    if (tid < nb) g_bsum[tid] = (v + base) - c;
}

__global__ void __launch_bounds__(SCAN_BS) scan3_kernel(int N, int E) {
    const int i = blockIdx.x * SCAN_BS + threadIdx.x;
    if (i < N) {
        const int o = g_offpart[i] + g_bsum[blockIdx.x];
        g_off[i] = o;
        g_cur[i] = o;
    }
    if (blockIdx.x == 0 && threadIdx.x == 0) g_off[N] = E;
}

// scatter indices AND edge_attr payload into dst-sorted order
__global__ void scatter_kernel(const int* __restrict__ ei,
                               const float4* __restrict__ ea4, int E) {
    int e = blockIdx.x * blockDim.x + threadIdx.x;
    if (e < E) {
        const int dst = ei[E + e];
        const int p = atomicAdd(&g_cur[dst], 1);
        g_src[p] = ei[e];
        const float4 q0 = ea4[(size_t)e * 4 + 0];
        const float4 q1 = ea4[(size_t)e * 4 + 1];
        const float4 q2 = ea4[(size_t)e * 4 + 2];
        const float4 q3 = ea4[(size_t)e * 4 + 3];
        float4* o = &g_easrt[(size_t)p * 4];
        o[0] = q0; o[1] = q1; o[2] = q2; o[3] = q3;
    }
}

// ---------------------------------------------------------------------------
// Phase B: per-node aggregation. One warp per node, lane owns cols (2l, 2l+1).
// Per <=32-edge chunk: coalesced cp.async of the contiguous 2KB ea window into
// shared (zero register cost), one wait, then 4-edge groups: 4 x-gathers in
// flight, FMAs read ea via broadcast LDS.
// ---------------------------------------------------------------------------
__global__ void __launch_bounds__(128) aggregate_kernel(
    const float* __restrict__ x,
    const float* __restrict__ be,       // [64]
    int N)
{
    __shared__ ull Wp[8 * DIM];                 // packed K-pairs of We
    __shared__ __align__(16) float4 sbuf[4][128];  // per-warp 2KB chunk buffer

    const int tid = threadIdx.x;
    // Wp is filled from g_Wp staged by a tiny kernel? No: stage from global We
    // (done below via constant pointer passed in — see launch; here Wp comes
    // from the global packed copy g_wpack)
    extern __device__ ull g_wpack[8 * DIM];
    for (int f = tid; f < 8 * DIM; f += 128) Wp[f] = g_wpack[f];
    __syncthreads();

    const int lane = tid & 31;
    const int wrp  = tid >> 5;
    const int c0 = lane * 2;
    const int n = (blockIdx.x * blockDim.x + tid) >> 5;
    if (n >= N) return;

    ull wA[8], wB[8];
#pragma unroll
    for (int k2 = 0; k2 < 8; k2++) {
        wA[k2] = Wp[k2 * 64 + c0];
        wB[k2] = Wp[k2 * 64 + c0 + 1];
    }
    const float2 bev = *reinterpret_cast<const float2*>(be + c0);

    const int beg = g_off[n];
    const int end = g_off[n + 1];
    const float2 xn = *reinterpret_cast<const float2*>(x + (size_t)n * DIM + c0);

    const unsigned sb = smem_u32(&sbuf[wrp][0]);
    const char* ea_bytes = reinterpret_cast<const char*>(g_easrt);
    const ulonglong2* sb_u2 = reinterpret_cast<const ulonglong2*>(&sbuf[wrp][0]);

    float acc0 = 0.f, acc1 = 0.f;

    for (int base = beg; base < end; base += 32) {
        const int m = min(32, end - base);
        int src_l = 0;
        if (base + lane < end) src_l = g_src[base + lane];

        // coalesced prefetch of the contiguous m*64B ea window
        const unsigned bytes = (unsigned)m * 64u;
#pragma unroll
        for (int q = 0; q < 4; q++) {
            const unsigned off = q * 512u + (unsigned)lane * 16u;
            if (off < bytes)
                cpa16(sb + off, ea_bytes + (size_t)base * 64 + off);
        }
        asm volatile("cp.async.commit_group;");
        asm volatile("cp.async.wait_group 0;");
        __syncwarp();

        for (int j = 0; j < m; j += 4) {
            int s[4]; float vf[4];
#pragma unroll
            for (int k = 0; k < 4; k++) {
                s[k]  = __shfl_sync(0xFFFFFFFFu, src_l, j + k);
                vf[k] = (j + k < m) ? 1.f : 0.f;
            }
            float2 xv[4];
#pragma unroll
            for (int k = 0; k < 4; k++)
                xv[k] = *reinterpret_cast<const float2*>(x + (size_t)s[k] * DIM + c0);

            ull A[4], B[4];
#pragma unroll
            for (int k = 0; k < 4; k++) { A[k] = 0ull; B[k] = 0ull; }
#pragma unroll
            for (int k2p = 0; k2p < 4; k2p++) {
#pragma unroll
                for (int k = 0; k < 4; k++) {
                    const ulonglong2 u = sb_u2[(j + k) * 4 + k2p];  // broadcast LDS.128
                    ffma2(A[k], u.x, wA[2 * k2p]);
                    ffma2(B[k], u.x, wB[2 * k2p]);
                    ffma2(A[k], u.y, wA[2 * k2p + 1]);
                    ffma2(B[k], u.y, wB[2 * k2p + 1]);
                }
            }
#pragma unroll
            for (int k = 0; k < 4; k++) {
                float lo0, hi0, lo1, hi1;
                upk2(lo0, hi0, A[k]);
                upk2(lo1, hi1, B[k]);
                acc0 += vf[k] * fmaxf(xv[k].x + (lo0 + hi0 + bev.x), 0.f);
                acc1 += vf[k] * fmaxf(xv[k].y + (lo1 + hi1 + bev.y), 0.f);
            }
        }
        __syncwarp();   // sbuf reuse safety for next chunk
    }

    *reinterpret_cast<float2*>(g_h + (size_t)n * DIM + c0) =
        make_float2(xn.x + acc0, xn.y + acc1);
}

// packed We staging (runs once per call, tiny)
__device__ ull g_wpack[8 * DIM];
__global__ void pack_we_kernel(const float* __restrict__ We) {
    const int f = blockIdx.x * blockDim.x + threadIdx.x;
    if (f < 8 * DIM) {
        const int k2 = f >> 6, j = f & 63;
        g_wpack[f] = pk2(We[(2 * k2) * DIM + j], We[(2 * k2 + 1) * DIM + j]);
    }
}

// ---------------------------------------------------------------------------
// Phase C: out = relu(h@W1 + b1) @ W2 + b2   (unchanged, proven)
// ---------------------------------------------------------------------------
#define HS_LD 68
#define MLP_SMEM (128 * HS_LD * 4 + 32 * 64 * 8)

__global__ void __launch_bounds__(256) mlp_kernel(
    const float* __restrict__ W1, const float* __restrict__ b1,
    const float* __restrict__ W2, const float* __restrict__ b2,
    float* __restrict__ out, int N)
{
    extern __shared__ float smem[];
    float* hs = smem;
    ull*   Wp = reinterpret_cast<ull*>(smem + 128 * HS_LD);

    const int tid = threadIdx.x;
    const int nb = blockIdx.x * 128;

#pragma unroll
    for (int f = tid; f < 128 * 16; f += 256) {
        const int i = f >> 4, c4 = f & 15;
        float4 v = make_float4(0.f, 0.f, 0.f, 0.f);
        if (nb + i < N) v = reinterpret_cast<const float4*>(g_h)[(size_t)(nb + i) * 16 + c4];
        *reinterpret_cast<float4*>(hs + i * HS_LD + c4 * 4) = v;
    }
    for (int f = tid; f < 2048; f += 256) {
        const int k2 = f >> 6, j = f & 63;
        Wp[f] = pk2(W1[(2 * k2) * DIM + j], W1[(2 * k2 + 1) * DIM + j]);
    }
    __syncthreads();

    const int rg = tid >> 4, jg = tid & 15;
    const int i0 = rg * 8, j0 = jg * 4;
    float t[8][4];

    {
        ull acc[8][4];
#pragma unroll
        for (int ii = 0; ii < 8; ii++)
#pragma unroll
            for (int jj = 0; jj < 4; jj++) acc[ii][jj] = 0ull;
#pragma unroll 8
        for (int k2 = 0; k2 < 32; k2++) {
            ull hv[8];
#pragma unroll
            for (int ii = 0; ii < 8; ii++)
                hv[ii] = *reinterpret_cast<const ull*>(hs + (i0 + ii) * HS_LD + 2 * k2);
            const ulonglong2 w01 = *reinterpret_cast<const ulonglong2*>(Wp + k2 * 64 + j0);
            const ulonglong2 w23 = *reinterpret_cast<const ulonglong2*>(Wp + k2 * 64 + j0 + 2);
            ull wv[4] = { w01.x, w01.y, w23.x, w23.y };
#pragma unroll
            for (int ii = 0; ii < 8; ii++)
#pragma unroll
                for (int jj = 0; jj < 4; jj++) ffma2(acc[ii][jj], hv[ii], wv[jj]);
        }
        const float4 bb = *reinterpret_cast<const float4*>(b1 + j0);
        const float bbv[4] = { bb.x, bb.y, bb.z, bb.w };
#pragma unroll
        for (int ii = 0; ii < 8; ii++)
#pragma unroll
            for (int jj = 0; jj < 4; jj++) {
                float lo, hi;
                upk2(lo, hi, acc[ii][jj]);
                t[ii][jj] = fmaxf(lo + hi + bbv[jj], 0.f);
            }
    }
    __syncthreads();

#pragma unroll
    for (int ii = 0; ii < 8; ii++)
        *reinterpret_cast<float4*>(hs + (i0 + ii) * HS_LD + j0) =
            make_float4(t[ii][0], t[ii][1], t[ii][2], t[ii][3]);
    for (int f = tid; f < 2048; f += 256) {
        const int k2 = f >> 6, j = f & 63;
        Wp[f] = pk2(W2[(2 * k2) * DIM + j], W2[(2 * k2 + 1) * DIM + j]);
    }
    __syncthreads();

    {
        ull acc[8][4];
#pragma unroll
        for (int ii = 0; ii < 8; ii++)
#pragma unroll
            for (int jj = 0; jj < 4; jj++) acc[ii][jj] = 0ull;
#pragma unroll 8
        for (int k2 = 0; k2 < 32; k2++) {
            ull hv[8];
#pragma unroll
            for (int ii = 0; ii < 8; ii++)
                hv[ii] = *reinterpret_cast<const ull*>(hs + (i0 + ii) * HS_LD + 2 * k2);
            const ulonglong2 w01 = *reinterpret_cast<const ulonglong2*>(Wp + k2 * 64 + j0);
            const ulonglong2 w23 = *reinterpret_cast<const ulonglong2*>(Wp + k2 * 64 + j0 + 2);
            ull wv[4] = { w01.x, w01.y, w23.x, w23.y };
#pragma unroll
            for (int ii = 0; ii < 8; ii++)
#pragma unroll
                for (int jj = 0; jj < 4; jj++) ffma2(acc[ii][jj], hv[ii], wv[jj]);
        }
        const float4 bb = *reinterpret_cast<const float4*>(b2 + j0);
        const float bbv[4] = { bb.x, bb.y, bb.z, bb.w };
#pragma unroll
        for (int ii = 0; ii < 8; ii++) {
            const int n = nb + i0 + ii;
            if (n < N) {
                float r[4];
#pragma unroll
                for (int jj = 0; jj < 4; jj++) {
                    float lo, hi;
                    upk2(lo, hi, acc[ii][jj]);
                    r[jj] = lo + hi + bbv[jj];
                }
                *reinterpret_cast<float4*>(out + (size_t)n * DIM + j0) =
                    make_float4(r[0], r[1], r[2], r[3]);
            }
        }
    }
}

// ---------------------------------------------------------------------------
extern "C" void kernel_launch(void* const* d_in, const int* in_sizes, int n_in,
                              void* d_out, int out_size)
{
    const float* x  = (const float*)d_in[0];
    const int*   ei = (const int*)d_in[1];        // int32 (JAX x64 disabled)
    const float* ea = (const float*)d_in[2];
    const float* We = (const float*)d_in[3];
    const float* be = (const float*)d_in[4];
    const float* W1 = (const float*)d_in[5];
    const float* b1 = (const float*)d_in[6];
    const float* W2 = (const float*)d_in[7];
    const float* b2 = (const float*)d_in[8];
    float* out = (float*)d_out;

    const int N = in_sizes[0] / DIM;       // 100000
    const int E = in_sizes[1] / 2;         // 1600000

    const int nbN   = (N + 255) / 256;
    const int nbE   = (E + 255) / 256;
    const int nbScn = (N + SCAN_BS - 1) / SCAN_BS;   // 98 (<=128)

    // A) dst-bucket counting sort with edge_attr payload
    zero_cnt_kernel<<<nbN, 256>>>(N);
    hist_kernel<<<nbE, 256>>>(ei, E);
    scan1_kernel<<<nbScn, SCAN_BS>>>(N);
    scan2_kernel<<<1, 128>>>(nbScn);
    scan3_kernel<<<nbScn, SCAN_BS>>>(N, E);
    pack_we_kernel<<<2, 256>>>(We);
    scatter_kernel<<<nbE, 256>>>(ei, reinterpret_cast<const float4*>(ea), E);

    // B) gather-side aggregation: warp per node, cp.async chunk pipeline
    aggregate_kernel<<<(N * 32 + 127) / 128, 128>>>(x, be, N);

    // C) node MLP
    cudaFuncSetAttribute(mlp_kernel, cudaFuncAttributeMaxDynamicSharedMemorySize, MLP_SMEM);
    mlp_kernel<<<(N + 127) / 128, 256, MLP_SMEM>>>(W1, b1, W2, b2, out, N);
}